// round 16
// baseline (speedup 1.0000x reference)
#include <cuda_runtime.h>
#include <math.h>

// ---------------------------------------------------------------------------
// SinkhornLoss: m=8, n=2048, d=3, eps=1e-3, 50 iters, early-stop flag.
// chain(i,k) = 2c*x_i.y_k + c*pot_k - c*||col_k||^2, c = log2e/eps.
// R15: PERSISTENT KERNEL. All 50 iterations + loss run in ONE launch of 2048
// co-resident blocks (64 thr, __launch_bounds__(64,14): 14*148=2072 slots),
// synchronized by a software grid barrier (arrival counter + __ldcg spin).
// Static coords {c0,c1,c2,-c*n2} stay L1-resident across all passes (L1 is
// only flushed at launch boundaries); dynamic potentials are read with
// __ldcg (L2 = coherence point) and ordered by __threadfence before arrive.
// Keeps R12's one-pass adaptive LSE + per-tile exp skip + corrective redo.
// ---------------------------------------------------------------------------

#define MB     8
#define NB     2048
#define EPSF   1e-3f
#define THRESH 1e-3f
#define NITERS 50
#define CSC    1442.6950408889634f      // log2(e)/eps
#define INVC   6.931471805599453e-4f    // 1/CSC = eps*ln2
#define SMV_MIN 1.8189894e-12f          // 2^-39: validity floor for one-pass sum
#define SKIPT  (-60.0f)                 // per-tile skip threshold (log2 units)

#define ROWS   8                         // rows per block (4 f32x2 pairs)
#define PAIRS  (ROWS / 2)
#define WPB    2                         // warps per block (column split)
#define THREADS (WPB * 32)
#define CPW    (NB / WPB)                // 1024 columns per warp
#define TPW    (CPW / 32)                // 32 tile iters per warp
#define RGPB   (NB / ROWS)               // 256 row-groups per batch
#define GRID_HALF (MB * RGPB)            // 2048 blocks (ALL co-resident)

typedef unsigned long long u64;

// Scratch (allocation-free rule: __device__ globals)
__device__ float4   g_cx[MB * NB];  // {x0,x1,x2, -c*||x||^2}  STATIC after init
__device__ float4   g_cy[MB * NB];  // {y0,y1,y2, -c*||y||^2}  STATIC after init
__device__ float    g_n2x[MB * NB]; // c*||x||^2 (exact)
__device__ float    g_n2y[MB * NB];
__device__ float    g_shx[MB * NB]; // per-row predicted shift (own-block state)
__device__ float    g_shy[MB * NB];
__device__ float    g_lsx[MB * NB]; // per-row previous true lse (chain units)
__device__ float    g_lsy[MB * NB];
__device__ float    g_u[MB * NB];   // potentials (cross-block: read via __ldcg)
__device__ float    g_v[MB * NB];
__device__ float    g_la[MB * NB];
__device__ float    g_lb[MB * NB];
__device__ unsigned g_err[NITERS];  // per-iter max(err_u, err_v), float bits
__device__ unsigned g_ctr[2 * NITERS]; // grid-barrier arrival counters

__device__ __forceinline__ float ex2f(float x) {
    float r; asm("ex2.approx.ftz.f32 %0, %1;" : "=f"(r) : "f"(x)); return r;
}
__device__ __forceinline__ u64 pack2(float lo, float hi) {
    u64 r; asm("mov.b64 %0, {%1, %2};" : "=l"(r) : "f"(lo), "f"(hi)); return r;
}
__device__ __forceinline__ float lo2(u64 p) {
    float l, h; asm("mov.b64 {%0, %1}, %2;" : "=f"(l), "=f"(h) : "l"(p)); return l;
}
__device__ __forceinline__ float hi2(u64 p) {
    float l, h; asm("mov.b64 {%0, %1}, %2;" : "=f"(l), "=f"(h) : "l"(p)); return h;
}
__device__ __forceinline__ u64 fma2(u64 a, u64 b, u64 c) {
    u64 d; asm("fma.rn.f32x2 %0, %1, %2, %3;" : "=l"(d) : "l"(a), "l"(b), "l"(c)); return d;
}
__device__ __forceinline__ u64 add2(u64 a, u64 b) {
    u64 d; asm("add.rn.f32x2 %0, %1, %2;" : "=l"(d) : "l"(a), "l"(b)); return d;
}

// ---------------------------------------------------------------------------
__global__ void k_init(const float* __restrict__ px, const float* __restrict__ py,
                       const float* __restrict__ a, const float* __restrict__ b,
                       float* __restrict__ out) {
    int i = blockIdx.x * blockDim.x + threadIdx.x;
    if (i < MB * NB) {
        float x0 = px[3 * i], x1 = px[3 * i + 1], x2 = px[3 * i + 2];
        float n2x = CSC * (x0 * x0 + x1 * x1 + x2 * x2);
        g_cx[i] = make_float4(x0, x1, x2, -n2x);
        g_n2x[i] = n2x;
        float y0 = py[3 * i], y1 = py[3 * i + 1], y2 = py[3 * i + 2];
        float n2y = CSC * (y0 * y0 + y1 * y1 + y2 * y2);
        g_cy[i] = make_float4(y0, y1, y2, -n2y);
        g_n2y[i] = n2y;
        g_shx[i] = 0.0f;     // prediction (iter 0 redoes via validity check)
        g_shy[i] = 0.0f;
        g_lsx[i] = 0.0f;
        g_lsy[i] = 0.0f;
        g_u[i] = 0.0f;
        g_v[i] = 0.0f;
        g_la[i] = logf(a[i]);
        g_lb[i] = logf(b[i]);
    }
    if (i < NITERS)     g_err[i] = 0u;
    if (i < 2 * NITERS) g_ctr[i] = 0u;
    if (i < MB)         out[i] = 0.0f;
}

// ---------------------------------------------------------------------------
// Software grid barrier: all GRID_HALF blocks arrive at counter idx.
__device__ __forceinline__ void gbar(int idx) {
    __syncthreads();
    if (threadIdx.x == 0) {
        __threadfence();                         // order finalize stores
        atomicAdd(&g_ctr[idx], 1u);
        while (__ldcg(&g_ctr[idx]) < (unsigned)GRID_HALF) __nanosleep(64);
        __threadfence();
    }
    __syncthreads();
}

// ---------------------------------------------------------------------------
// One half Sinkhorn update (device function; SIDE=0 updates u, SIDE=1 v).
template <int SIDE>
__device__ __forceinline__ void half_iter(int iter, int batch, int row0, int base,
                                          int warp, int lane) {
    __shared__ float s_sm[WPB][ROWS];
    __shared__ float s_mx[WPB][ROWS];

    const float4* __restrict__ rp  = SIDE ? g_cy : g_cx;   // row-side coords (static)
    const float4* __restrict__ cp  = SIDE ? g_cx : g_cy;   // col-side coords (static)
    const float*               pot = SIDE ? g_u : g_v;     // col-side potential (__ldcg)
    const float*  __restrict__ n2  = SIDE ? g_n2y : g_n2x; // c*||row||^2
    float*                     shp = SIDE ? g_shy : g_shx; // predicted shift (own rows)
    float*                     lsp = SIDE ? g_lsy : g_lsx; // previous lse (own rows)
    float*                     upd = SIDE ? g_v : g_u;     // potential being updated
    const float*  __restrict__ rl  = SIDE ? g_lb : g_la;   // row-side log marginal

    // Row-pair packed coordinates (pre-scaled by 2c) and packed -shift
    u64 cx2[PAIRS], cy2[PAIRS], cz2[PAIRS], nsh2[PAIRS];
    float sm[ROWS];
#pragma unroll
    for (int p = 0; p < PAIRS; p++) {
        float4 R0 = rp[base + row0 + 2 * p];
        float4 R1 = rp[base + row0 + 2 * p + 1];
        cx2[p] = pack2(R0.x * (2.0f * CSC), R1.x * (2.0f * CSC));
        cy2[p] = pack2(R0.y * (2.0f * CSC), R1.y * (2.0f * CSC));
        cz2[p] = pack2(R0.z * (2.0f * CSC), R1.z * (2.0f * CSC));
        nsh2[p] = pack2(-shp[base + row0 + 2 * p], -shp[base + row0 + 2 * p + 1]);
    }
#pragma unroll
    for (int j = 0; j < ROWS; j++) sm[j] = 0.0f;
    const int kbeg = base + warp * CPW + lane;

    // ---- Fused one-pass: sum of ex2(chain - shift_pred) with per-tile skip
#pragma unroll 2
    for (int t = 0; t < TPW; t++) {
        int k = kbeg + t * 32;
        float4 C = cp[k];                        // static: L1-resident
        float qb = fmaf(__ldcg(&pot[k]), CSC, C.w);
        u64 Cx = pack2(C.x, C.x), Cy = pack2(C.y, C.y), Cz = pack2(C.z, C.z);
        u64 Q  = pack2(qb, qb);
        u64 a2[PAIRS];
        float mx = -3.4e38f;
#pragma unroll
        for (int p = 0; p < PAIRS; p++) {
            u64 s2 = fma2(cx2[p], Cx, fma2(cy2[p], Cy, fma2(cz2[p], Cz, Q)));
            a2[p] = add2(s2, nsh2[p]);
            mx = fmaxf(mx, fmaxf(lo2(a2[p]), hi2(a2[p])));
        }
        if (__any_sync(0xffffffffu, mx > SKIPT)) {
#pragma unroll
            for (int p = 0; p < PAIRS; p++) {
                sm[2 * p]     += ex2f(lo2(a2[p]));
                sm[2 * p + 1] += ex2f(hi2(a2[p]));
            }
        }
    }
#pragma unroll
    for (int j = 0; j < ROWS; j++) {
#pragma unroll
        for (int o = 16; o; o >>= 1)
            sm[j] += __shfl_xor_sync(0xffffffffu, sm[j], o);
    }
    if (lane == 0) {
#pragma unroll
        for (int j = 0; j < ROWS; j++) s_sm[warp][j] = sm[j];
    }
    __syncthreads();

    // Validity from the sums alone
    bool redo = false;
    float smvr[ROWS];
#pragma unroll
    for (int j = 0; j < ROWS; j++) {
        smvr[j] = s_sm[0][j] + s_sm[1][j];
        redo = redo || !(smvr[j] >= SMV_MIN && smvr[j] <= 3.4e38f);
    }

    float amax[ROWS];
#pragma unroll
    for (int j = 0; j < ROWS; j++) amax[j] = 0.0f;

    if (redo) {
        // ---- Corrective two-pass: exact arg-max, then shifted (skipped) sum
        float mxs[ROWS];
#pragma unroll
        for (int j = 0; j < ROWS; j++) mxs[j] = -3.4e38f;
#pragma unroll 2
        for (int t = 0; t < TPW; t++) {
            int k = kbeg + t * 32;
            float4 C = cp[k];
            float qb = fmaf(__ldcg(&pot[k]), CSC, C.w);
            u64 Cx = pack2(C.x, C.x), Cy = pack2(C.y, C.y), Cz = pack2(C.z, C.z);
            u64 Q  = pack2(qb, qb);
#pragma unroll
            for (int p = 0; p < PAIRS; p++) {
                u64 s2 = fma2(cx2[p], Cx, fma2(cy2[p], Cy, fma2(cz2[p], Cz, Q)));
                u64 a2 = add2(s2, nsh2[p]);
                mxs[2 * p]     = fmaxf(mxs[2 * p],     lo2(a2));
                mxs[2 * p + 1] = fmaxf(mxs[2 * p + 1], hi2(a2));
            }
        }
#pragma unroll
        for (int j = 0; j < ROWS; j++) {
#pragma unroll
            for (int o = 16; o; o >>= 1)
                mxs[j] = fmaxf(mxs[j], __shfl_xor_sync(0xffffffffu, mxs[j], o));
        }
        if (lane == 0) {
#pragma unroll
            for (int j = 0; j < ROWS; j++) s_mx[warp][j] = mxs[j];
        }
        __syncthreads();
        u64 nmx2[PAIRS];
#pragma unroll
        for (int j = 0; j < ROWS; j++)
            amax[j] = fmaxf(s_mx[0][j], s_mx[1][j]);
#pragma unroll
        for (int p = 0; p < PAIRS; p++)
            nmx2[p] = add2(nsh2[p], pack2(-amax[2 * p], -amax[2 * p + 1]));
#pragma unroll
        for (int j = 0; j < ROWS; j++) sm[j] = 0.0f;
#pragma unroll 2
        for (int t = 0; t < TPW; t++) {
            int k = kbeg + t * 32;
            float4 C = cp[k];
            float qb = fmaf(__ldcg(&pot[k]), CSC, C.w);
            u64 Cx = pack2(C.x, C.x), Cy = pack2(C.y, C.y), Cz = pack2(C.z, C.z);
            u64 Q  = pack2(qb, qb);
            u64 a2[PAIRS];
            float mx = -3.4e38f;
#pragma unroll
            for (int p = 0; p < PAIRS; p++) {
                u64 s2 = fma2(cx2[p], Cx, fma2(cy2[p], Cy, fma2(cz2[p], Cz, Q)));
                a2[p] = add2(s2, nmx2[p]);
                mx = fmaxf(mx, fmaxf(lo2(a2[p]), hi2(a2[p])));
            }
            if (__any_sync(0xffffffffu, mx > SKIPT)) {   // exact max: smv>=1
#pragma unroll
                for (int p = 0; p < PAIRS; p++) {
                    sm[2 * p]     += ex2f(lo2(a2[p]));
                    sm[2 * p + 1] += ex2f(hi2(a2[p]));
                }
            }
        }
#pragma unroll
        for (int j = 0; j < ROWS; j++) {
#pragma unroll
            for (int o = 16; o; o >>= 1)
                sm[j] += __shfl_xor_sync(0xffffffffu, sm[j], o);
        }
        if (lane == 0) {
#pragma unroll
            for (int j = 0; j < ROWS; j++) s_sm[warp][j] = sm[j];
        }
        __syncthreads();
    }

    // ---- Finalize: warp 0, lanes 0..7 each own one row
    if (warp == 0 && lane < ROWS) {
        int r = base + row0 + lane;
        float smv = redo ? (s_sm[0][lane] + s_sm[1][lane]) : smvr[lane];
        float lse = shp[r] + amax[lane] + __log2f(smv);  // true chain lse
        float n2r = n2[r];                               // c*||row||^2 (exact)
        float nv = fmaf(n2r - lse, INVC, EPSF * rl[r]);
        float ov = upd[r];
        upd[r] = nv;                                     // visible at L2 (write-through)
        float lse_old = lsp[r];
        lsp[r] = lse;
        shp[r] = (iter == 0) ? lse : (lse + (lse - lse_old));
        float e = fabsf(nv - ov);
#pragma unroll
        for (int o = 4; o; o >>= 1)
            e = fmaxf(e, __shfl_xor_sync(0x000000ffu, e, o));
        if (lane == 0)
            atomicMax(&g_err[iter], __float_as_uint(e)); // e>=0: uint order==float order
    }
}

// ---------------------------------------------------------------------------
// Persistent kernel: 50 Sinkhorn iterations + loss, one launch.
__global__ void __launch_bounds__(THREADS, 14) k_sink(float* __restrict__ out) {
    const int warp  = threadIdx.x >> 5;
    const int lane  = threadIdx.x & 31;
    const int batch = blockIdx.x / RGPB;
    const int row0  = (blockIdx.x % RGPB) * ROWS;
    const int base  = batch * NB;

    for (int iter = 0; iter < NITERS; iter++) {
        if (iter > 0) {
            // g_err[iter-1] complete after the previous gbar; uniform decision
            if (__uint_as_float(__ldcg(&g_err[iter - 1])) < THRESH) break;
        }
        half_iter<0>(iter, batch, row0, base, warp, lane);
        gbar(2 * iter);
        half_iter<1>(iter, batch, row0, base, warp, lane);
        gbar(2 * iter + 1);
    }

    // ---- loss[b] = sum_{i,k} M * exp((u_i + v_k - M)/eps), with tile skip
    float cx[ROWS], cy[ROWS], cz[ROWS], aj[ROWS], U[ROWS];
#pragma unroll
    for (int j = 0; j < ROWS; j++) {
        float4 R = g_cx[base + row0 + j];            // {x, -c*x2} static
        cx[j] = R.x * (2.0f * CSC);
        cy[j] = R.y * (2.0f * CSC);
        cz[j] = R.z * (2.0f * CSC);
        U[j]  = g_u[base + row0 + j];                // own rows
        aj[j] = fmaf(U[j], CSC, R.w);                // c*u - c*x2
    }
    const int kbeg = base + warp * CPW + lane;

    float tot = 0.0f;
#pragma unroll 2
    for (int t = 0; t < TPW; t++) {
        int k = kbeg + t * 32;
        float4 C = g_cy[k];                          // {y, -c*y2} static
        float vk = __ldcg(&g_v[k]);                  // cross-block
        float qv = fmaf(vk, CSC, C.w);               // c*v - c*y2
        float carg[ROWS];
        float mx = -3.4e38f;
#pragma unroll
        for (int j = 0; j < ROWS; j++) {
            carg[j] = fmaf(cx[j], C.x, fmaf(cy[j], C.y, fmaf(cz[j], C.z, qv + aj[j])));
            mx = fmaxf(mx, carg[j]);
        }
        if (__any_sync(0xffffffffu, mx > SKIPT)) {
#pragma unroll
            for (int j = 0; j < ROWS; j++) {
                float e  = ex2f(carg[j]);
                float uv = U[j] + vk;
                float Mv = fmaf(carg[j], -INVC, uv); // = M (unclamped)
                tot = fmaf(Mv, e, tot);
            }
        }
    }
#pragma unroll
    for (int o = 16; o; o >>= 1)
        tot += __shfl_xor_sync(0xffffffffu, tot, o);
    if (lane == 0) atomicAdd(&out[batch], tot);
}

// ---------------------------------------------------------------------------
extern "C" void kernel_launch(void* const* d_in, const int* in_sizes, int n_in,
                              void* d_out, int out_size) {
    (void)in_sizes; (void)n_in; (void)out_size;
    const float* px = (const float*)d_in[0];   // predicted [8,2048,3]
    const float* py = (const float*)d_in[1];   // expected  [8,2048,3]
    const float* a  = (const float*)d_in[2];   // [8,2048]
    const float* b  = (const float*)d_in[3];   // [8,2048]
    float* out = (float*)d_out;                // [8]

    k_init<<<(MB * NB + 255) / 256, 256>>>(px, py, a, b, out);
    k_sink<<<GRID_HALF, THREADS>>>(out);
}

// round 17
// speedup vs baseline: 1.7577x; 1.7577x over previous
#include <cuda_runtime.h>
#include <math.h>

// ---------------------------------------------------------------------------
// SinkhornLoss: m=8, n=2048, d=3, eps=1e-3, 50 iters, early-stop flag.
// chain(i,k) = 2c*x_i.y_k + qb_k, qb_k = c*pot_k - c*||col_k||^2, c=log2e/eps.
// R16 = R14 (best: one-pass adaptive LSE + per-tile exp skip + redo) with:
//   (1) iter-0 fast path: shift=0 makes the speculative sum overflow with
//       certainty, so go straight to the exact two-pass (same numerics);
//   (2) finalize-operand prefetch (n2, log-marginal, prev-lse) issued before
//       the shfl reductions so their latency hides under the reduce chain
//       instead of extending the per-launch tail.
// ---------------------------------------------------------------------------

#define MB     8
#define NB     2048
#define EPSF   1e-3f
#define THRESH 1e-3f
#define NITERS 50
#define CSC    1442.6950408889634f      // log2(e)/eps
#define INVC   6.931471805599453e-4f    // 1/CSC = eps*ln2
#define SMV_MIN 1.8189894e-12f          // 2^-39: validity floor for one-pass sum
#define SKIPT  (-60.0f)                 // per-tile skip threshold (log2 units)

#define ROWS   8                         // rows per block (4 f32x2 pairs)
#define PAIRS  (ROWS / 2)
#define WPB    2                         // warps per block (column split)
#define THREADS (WPB * 32)
#define CPW    (NB / WPB)                // 1024 columns per warp
#define TPW    (CPW / 32)                // 32 tile iters per warp
#define RGPB   (NB / ROWS)               // 256 row-groups per batch
#define GRID_HALF (MB * RGPB)            // 2048 blocks

typedef unsigned long long u64;

// Scratch (allocation-free rule: __device__ globals)
__device__ float4   g_cx[MB * NB];  // {x0,x1,x2, c*u - c*||x||^2}
__device__ float4   g_cy[MB * NB];  // {y0,y1,y2, c*v - c*||y||^2}
__device__ float    g_n2x[MB * NB]; // c*||x||^2 (exact, no drift)
__device__ float    g_n2y[MB * NB]; // c*||y||^2
__device__ float    g_shx[MB * NB]; // per-row predicted shift (u-update rows)
__device__ float    g_shy[MB * NB];
__device__ float    g_lsx[MB * NB]; // per-row previous true lse (chain units)
__device__ float    g_lsy[MB * NB];
__device__ float    g_u[MB * NB];
__device__ float    g_v[MB * NB];
__device__ float    g_la[MB * NB];
__device__ float    g_lb[MB * NB];
__device__ unsigned g_err[NITERS];  // per-iter max(err_u, err_v), float bits

__device__ __forceinline__ float ex2f(float x) {
    float r; asm("ex2.approx.ftz.f32 %0, %1;" : "=f"(r) : "f"(x)); return r;
}
__device__ __forceinline__ u64 pack2(float lo, float hi) {
    u64 r; asm("mov.b64 %0, {%1, %2};" : "=l"(r) : "f"(lo), "f"(hi)); return r;
}
__device__ __forceinline__ float lo2(u64 p) {
    float l, h; asm("mov.b64 {%0, %1}, %2;" : "=f"(l), "=f"(h) : "l"(p)); return l;
}
__device__ __forceinline__ float hi2(u64 p) {
    float l, h; asm("mov.b64 {%0, %1}, %2;" : "=f"(l), "=f"(h) : "l"(p)); return h;
}
__device__ __forceinline__ u64 fma2(u64 a, u64 b, u64 c) {
    u64 d; asm("fma.rn.f32x2 %0, %1, %2, %3;" : "=l"(d) : "l"(a), "l"(b), "l"(c)); return d;
}
__device__ __forceinline__ u64 add2(u64 a, u64 b) {
    u64 d; asm("add.rn.f32x2 %0, %1, %2;" : "=l"(d) : "l"(a), "l"(b)); return d;
}

// ---------------------------------------------------------------------------
__global__ void k_init(const float* __restrict__ px, const float* __restrict__ py,
                       const float* __restrict__ a, const float* __restrict__ b,
                       float* __restrict__ out) {
    int i = blockIdx.x * blockDim.x + threadIdx.x;
    if (i < MB * NB) {
        float x0 = px[3 * i], x1 = px[3 * i + 1], x2 = px[3 * i + 2];
        float n2x = CSC * (x0 * x0 + x1 * x1 + x2 * x2);
        g_cx[i] = make_float4(x0, x1, x2, -n2x);     // u = 0
        g_n2x[i] = n2x;
        float y0 = py[3 * i], y1 = py[3 * i + 1], y2 = py[3 * i + 2];
        float n2y = CSC * (y0 * y0 + y1 * y1 + y2 * y2);
        g_cy[i] = make_float4(y0, y1, y2, -n2y);     // v = 0
        g_n2y[i] = n2y;
        g_shx[i] = 0.0f;
        g_shy[i] = 0.0f;
        g_lsx[i] = 0.0f;
        g_lsy[i] = 0.0f;
        g_u[i] = 0.0f;
        g_v[i] = 0.0f;
        g_la[i] = logf(a[i]);
        g_lb[i] = logf(b[i]);
    }
    if (i < NITERS) g_err[i] = 0u;
    if (i < MB)     out[i] = 0.0f;
}

// ---------------------------------------------------------------------------
// One half Sinkhorn update. SIDE=0 updates u (rows=x, cols=y+v);
//                           SIDE=1 updates v (rows=y, cols=x+u).
// Freeze: once g_err[s] < THRESH, later launches return untouched (slots stay
// 0 < THRESH -> sticky), matching the reference's done flag.
template <int SIDE>
__global__ void __launch_bounds__(THREADS, 14) k_half(int iter) {
    if (iter > 0 && __uint_as_float(g_err[iter - 1]) < THRESH) return;

    __shared__ float s_sm[WPB][ROWS];
    __shared__ float s_mx[WPB][ROWS];

    const int warp  = threadIdx.x >> 5;
    const int lane  = threadIdx.x & 31;
    const int batch = blockIdx.x / RGPB;
    const int row0  = (blockIdx.x % RGPB) * ROWS;
    const int base  = batch * NB;

    const float4* __restrict__ rp  = SIDE ? g_cy : g_cx;   // row-side coords
    const float4* __restrict__ cp  = SIDE ? g_cx : g_cy;   // col-side {coords, qb}
    float4*                    rw  = SIDE ? g_cy : g_cx;   // row-side (finalize .w write)
    const float*  __restrict__ n2  = SIDE ? g_n2y : g_n2x; // c*||row||^2
    float*                     shp = SIDE ? g_shy : g_shx; // predicted shift
    float*                     lsp = SIDE ? g_lsy : g_lsx; // previous lse
    float*                     upd = SIDE ? g_v : g_u;     // potential being updated
    const float*  __restrict__ rl  = SIDE ? g_lb : g_la;   // row-side log marginal

    // Row-pair packed coordinates (pre-scaled by 2c) and packed -shift
    u64 cx2[PAIRS], cy2[PAIRS], cz2[PAIRS], nsh2[PAIRS];
    float sm[ROWS];
#pragma unroll
    for (int p = 0; p < PAIRS; p++) {
        float4 R0 = rp[base + row0 + 2 * p];
        float4 R1 = rp[base + row0 + 2 * p + 1];
        cx2[p] = pack2(R0.x * (2.0f * CSC), R1.x * (2.0f * CSC));
        cy2[p] = pack2(R0.y * (2.0f * CSC), R1.y * (2.0f * CSC));
        cz2[p] = pack2(R0.z * (2.0f * CSC), R1.z * (2.0f * CSC));
        nsh2[p] = pack2(-shp[base + row0 + 2 * p], -shp[base + row0 + 2 * p + 1]);
    }
#pragma unroll
    for (int j = 0; j < ROWS; j++) sm[j] = 0.0f;
    const int kbeg = base + warp * CPW + lane;

    // Finalize-operand prefetch slots (filled before the reductions so load
    // latency hides under the shfl chains)
    float f_n2 = 0.0f, f_rl = 0.0f, f_ls = 0.0f;

    bool redo;
    float smvr[ROWS];
#pragma unroll
    for (int j = 0; j < ROWS; j++) smvr[j] = 0.0f;

    if (iter > 0) {
        // ---- Fused one-pass: sum of ex2(chain - shift_pred), per-tile skip
#pragma unroll 2
        for (int t = 0; t < TPW; t++) {
            int k = kbeg + t * 32;
            float4 C = cp[k];                        // {c0,c1,c2, qb}
            u64 Cx = pack2(C.x, C.x), Cy = pack2(C.y, C.y), Cz = pack2(C.z, C.z);
            u64 Q  = pack2(C.w, C.w);
            u64 a2[PAIRS];
            float mx = -3.4e38f;
#pragma unroll
            for (int p = 0; p < PAIRS; p++) {
                u64 s2 = fma2(cx2[p], Cx, fma2(cy2[p], Cy, fma2(cz2[p], Cz, Q)));
                a2[p] = add2(s2, nsh2[p]);
                mx = fmaxf(mx, fmaxf(lo2(a2[p]), hi2(a2[p])));
            }
            if (__any_sync(0xffffffffu, mx > SKIPT)) {
#pragma unroll
                for (int p = 0; p < PAIRS; p++) {
                    sm[2 * p]     += ex2f(lo2(a2[p]));
                    sm[2 * p + 1] += ex2f(hi2(a2[p]));
                }
            }
        }
        // prefetch finalize operands (latency hides under the shfl reduce)
        if (warp == 0 && lane < ROWS) {
            int r = base + row0 + lane;
            f_n2 = n2[r]; f_rl = rl[r]; f_ls = lsp[r];
        }
#pragma unroll
        for (int j = 0; j < ROWS; j++) {
#pragma unroll
            for (int o = 16; o; o >>= 1)
                sm[j] += __shfl_xor_sync(0xffffffffu, sm[j], o);
        }
        if (lane == 0) {
#pragma unroll
            for (int j = 0; j < ROWS; j++) s_sm[warp][j] = sm[j];
        }
        __syncthreads();

        // Validity from the sums alone: prediction within [-39, +127] log2 units
        redo = false;
#pragma unroll
        for (int j = 0; j < ROWS; j++) {
            smvr[j] = s_sm[0][j] + s_sm[1][j];
            redo = redo || !(smvr[j] >= SMV_MIN && smvr[j] <= 3.4e38f);
        }
    } else {
        // Iter 0: shift=0 guarantees overflow in the speculative sum — go
        // straight to the exact two-pass (identical numerics, one pass saved).
        redo = true;
    }

    float amax[ROWS];
#pragma unroll
    for (int j = 0; j < ROWS; j++) amax[j] = 0.0f;

    if (redo) {
        // ---- Corrective two-pass: exact arg-max, then shifted (skipped) sum
        float mxs[ROWS];
#pragma unroll
        for (int j = 0; j < ROWS; j++) mxs[j] = -3.4e38f;
#pragma unroll 2
        for (int t = 0; t < TPW; t++) {
            int k = kbeg + t * 32;
            float4 C = cp[k];
            u64 Cx = pack2(C.x, C.x), Cy = pack2(C.y, C.y), Cz = pack2(C.z, C.z);
            u64 Q  = pack2(C.w, C.w);
#pragma unroll
            for (int p = 0; p < PAIRS; p++) {
                u64 s2 = fma2(cx2[p], Cx, fma2(cy2[p], Cy, fma2(cz2[p], Cz, Q)));
                u64 a2 = add2(s2, nsh2[p]);
                mxs[2 * p]     = fmaxf(mxs[2 * p],     lo2(a2));
                mxs[2 * p + 1] = fmaxf(mxs[2 * p + 1], hi2(a2));
            }
        }
        if (iter == 0 && warp == 0 && lane < ROWS) {   // prefetch (iter-0 path)
            int r = base + row0 + lane;
            f_n2 = n2[r]; f_rl = rl[r]; f_ls = lsp[r];
        }
#pragma unroll
        for (int j = 0; j < ROWS; j++) {
#pragma unroll
            for (int o = 16; o; o >>= 1)
                mxs[j] = fmaxf(mxs[j], __shfl_xor_sync(0xffffffffu, mxs[j], o));
        }
        if (lane == 0) {
#pragma unroll
            for (int j = 0; j < ROWS; j++) s_mx[warp][j] = mxs[j];
        }
        __syncthreads();
        u64 nmx2[PAIRS];
#pragma unroll
        for (int j = 0; j < ROWS; j++)
            amax[j] = fmaxf(s_mx[0][j], s_mx[1][j]);
#pragma unroll
        for (int p = 0; p < PAIRS; p++)
            nmx2[p] = add2(nsh2[p], pack2(-amax[2 * p], -amax[2 * p + 1]));
#pragma unroll
        for (int j = 0; j < ROWS; j++) sm[j] = 0.0f;
#pragma unroll 2
        for (int t = 0; t < TPW; t++) {
            int k = kbeg + t * 32;
            float4 C = cp[k];
            u64 Cx = pack2(C.x, C.x), Cy = pack2(C.y, C.y), Cz = pack2(C.z, C.z);
            u64 Q  = pack2(C.w, C.w);
            u64 a2[PAIRS];
            float mx = -3.4e38f;
#pragma unroll
            for (int p = 0; p < PAIRS; p++) {
                u64 s2 = fma2(cx2[p], Cx, fma2(cy2[p], Cy, fma2(cz2[p], Cz, Q)));
                a2[p] = add2(s2, nmx2[p]);
                mx = fmaxf(mx, fmaxf(lo2(a2[p]), hi2(a2[p])));
            }
            if (__any_sync(0xffffffffu, mx > SKIPT)) {   // exact max: smv>=1
#pragma unroll
                for (int p = 0; p < PAIRS; p++) {
                    sm[2 * p]     += ex2f(lo2(a2[p]));
                    sm[2 * p + 1] += ex2f(hi2(a2[p]));
                }
            }
        }
#pragma unroll
        for (int j = 0; j < ROWS; j++) {
#pragma unroll
            for (int o = 16; o; o >>= 1)
                sm[j] += __shfl_xor_sync(0xffffffffu, sm[j], o);
        }
        if (lane == 0) {
#pragma unroll
            for (int j = 0; j < ROWS; j++) s_sm[warp][j] = sm[j];
        }
        __syncthreads();
    }

    // ---- Finalize: warp 0, lanes 0..7 each own one row
    if (warp == 0 && lane < ROWS) {
        int r = base + row0 + lane;
        float smv = redo ? (s_sm[0][lane] + s_sm[1][lane]) : smvr[lane];
        float lse = shp[r] + amax[lane] + __log2f(smv);  // true chain lse (amax=0 if !redo)
        float n2r = f_n2;                                // prefetched c*||row||^2
        float nv = fmaf(n2r - lse, INVC, EPSF * f_rl);
        float ov = upd[r];
        upd[r] = nv;
        // shift prediction for this row's NEXT same-side iteration
        lsp[r] = lse;
        shp[r] = (iter == 0) ? lse : (lse + (lse - f_ls));
        // refresh this row's column-side qb: c*pot_new - c*||row||^2
        ((float*)(rw + r))[3] = fmaf(CSC, nv, -n2r);
        float e = fabsf(nv - ov);
#pragma unroll
        for (int o = 4; o; o >>= 1)
            e = fmaxf(e, __shfl_xor_sync(0x000000ffu, e, o));
        if (lane == 0)
            atomicMax(&g_err[iter], __float_as_uint(e)); // e>=0: uint order==float order
    }
}

// ---------------------------------------------------------------------------
// loss[b] = sum_{i,k} M * exp((u_i + v_k - M)/eps)  with the same tile skip
__global__ void __launch_bounds__(THREADS, 14) k_loss(float* __restrict__ out) {
    const int warp  = threadIdx.x >> 5;
    const int lane  = threadIdx.x & 31;
    const int batch = blockIdx.x / RGPB;
    const int row0  = (blockIdx.x % RGPB) * ROWS;
    const int base  = batch * NB;

    float cx[ROWS], cy[ROWS], cz[ROWS], aj[ROWS], U[ROWS];
#pragma unroll
    for (int j = 0; j < ROWS; j++) {
        float4 R = g_cx[base + row0 + j];            // {x, c*u - c*x2}
        cx[j] = R.x * (2.0f * CSC);
        cy[j] = R.y * (2.0f * CSC);
        cz[j] = R.z * (2.0f * CSC);
        aj[j] = R.w;
        U[j]  = g_u[base + row0 + j];
    }
    const int kbeg = base + warp * CPW + lane;

    float tot = 0.0f;
#pragma unroll 2
    for (int t = 0; t < TPW; t++) {
        int k = kbeg + t * 32;
        float4 C = g_cy[k];                          // {y, c*v - c*y2}
        float vk = g_v[k];
        float carg[ROWS];
        float mx = -3.4e38f;
#pragma unroll
        for (int j = 0; j < ROWS; j++) {
            carg[j] = fmaf(cx[j], C.x, fmaf(cy[j], C.y, fmaf(cz[j], C.z, C.w + aj[j])));
            mx = fmaxf(mx, carg[j]);
        }
        if (__any_sync(0xffffffffu, mx > SKIPT)) {
#pragma unroll
            for (int j = 0; j < ROWS; j++) {
                float e  = ex2f(carg[j]);
                float uv = U[j] + vk;
                float Mv = fmaf(carg[j], -INVC, uv); // = M (unclamped)
                tot = fmaf(Mv, e, tot);
            }
        }
    }
#pragma unroll
    for (int o = 16; o; o >>= 1)
        tot += __shfl_xor_sync(0xffffffffu, tot, o);
    if (lane == 0) atomicAdd(&out[batch], tot);
}

// ---------------------------------------------------------------------------
extern "C" void kernel_launch(void* const* d_in, const int* in_sizes, int n_in,
                              void* d_out, int out_size) {
    (void)in_sizes; (void)n_in; (void)out_size;
    const float* px = (const float*)d_in[0];   // predicted [8,2048,3]
    const float* py = (const float*)d_in[1];   // expected  [8,2048,3]
    const float* a  = (const float*)d_in[2];   // [8,2048]
    const float* b  = (const float*)d_in[3];   // [8,2048]
    float* out = (float*)d_out;                // [8]

    k_init<<<(MB * NB + 255) / 256, 256>>>(px, py, a, b, out);
    for (int t = 0; t < NITERS; t++) {
        k_half<0><<<GRID_HALF, THREADS>>>(t);
        k_half<1><<<GRID_HALF, THREADS>>>(t);
    }
    k_loss<<<GRID_HALF, THREADS>>>(out);
}